// round 13
// baseline (speedup 1.0000x reference)
#include <cuda_runtime.h>
#include <cuda_bf16.h>
#include <cuda_fp16.h>
#include <cstdint>

#define N_NODES 200000
#define D_IN    256
#define D_OUT   256
#define BATCH   4096
#define K1      25
#define K2      10
#define M_L1    (BATCH * (1 + K2))   // 45056
#define KDIM    512                  // concat(self, agg) width

// ---------------- scratch (no allocations allowed) ----------------
__device__ __align__(16) __half         g_F16[(size_t)N_NODES * D_IN];   // 102 MB
__device__ __align__(16) __nv_bfloat16 g_X1hi[(size_t)M_L1 * KDIM];
__device__ __align__(16) __nv_bfloat16 g_X1lo[(size_t)M_L1 * KDIM];
__device__ __align__(16) float         g_h1[(size_t)M_L1 * D_OUT];
__device__ __align__(16) __nv_bfloat16 g_X2hi[(size_t)BATCH * KDIM];
__device__ __align__(16) __nv_bfloat16 g_X2lo[(size_t)BATCH * KDIM];
__device__ __align__(16) __nv_bfloat16 g_W1hi[(size_t)D_OUT * KDIM];
__device__ __align__(16) __nv_bfloat16 g_W1lo[(size_t)D_OUT * KDIM];
__device__ __align__(16) __nv_bfloat16 g_W2hi[(size_t)D_OUT * KDIM];
__device__ __align__(16) __nv_bfloat16 g_W2lo[(size_t)D_OUT * KDIM];
__device__ int g_is64;

// ================= base-ISA PTX helpers (sm_103 plain, no 'a' features) ======
__device__ __forceinline__ uint32_t smem_u32(const void* p) {
    uint32_t a;
    asm("{ .reg .u64 t; cvta.to.shared.u64 t, %1; cvt.u32.u64 %0, t; }" : "=r"(a) : "l"(p));
    return a;
}
__device__ __forceinline__ void cp16(uint32_t saddr, const void* gaddr) {
    asm volatile("cp.async.cg.shared.global [%0], [%1], 16;" :: "r"(saddr), "l"(gaddr) : "memory");
}
__device__ __forceinline__ void cp_commit() {
    asm volatile("cp.async.commit_group;" ::: "memory");
}
__device__ __forceinline__ void cp_wait1() {
    asm volatile("cp.async.wait_group 1;" ::: "memory");
}
__device__ __forceinline__ void ldsm_x4(uint32_t* r, uint32_t addr) {
    asm volatile("ldmatrix.sync.aligned.m8n8.x4.shared.b16 {%0,%1,%2,%3}, [%4];"
                 : "=r"(r[0]), "=r"(r[1]), "=r"(r[2]), "=r"(r[3]) : "r"(addr));
}
__device__ __forceinline__ void mma16816(float* c, const uint32_t* a, const uint32_t* b) {
    asm volatile("mma.sync.aligned.m16n8k16.row.col.f32.bf16.bf16.f32 "
                 "{%0,%1,%2,%3}, {%4,%5,%6,%7}, {%8,%9}, {%0,%1,%2,%3};"
                 : "+f"(c[0]), "+f"(c[1]), "+f"(c[2]), "+f"(c[3])
                 : "r"(a[0]), "r"(a[1]), "r"(a[2]), "r"(a[3]), "r"(b[0]), "r"(b[1]));
}

__device__ __forceinline__ int get_idx(const void* __restrict__ p, int i) {
    if (g_is64) return (int)((const long long*)p)[i];
    return ((const int*)p)[i];
}

// ---------------- fp32 -> bf16 hi/lo split ----------------
__device__ __forceinline__ void split2(float x, __nv_bfloat16* hi, __nv_bfloat16* lo) {
    __nv_bfloat16 h = __float2bfloat16(x);
    *hi = h;
    *lo = __float2bfloat16(x - __bfloat162float(h));
}

// ---------------- launch #1: split BOTH weight matrices + index-dtype probe --
__global__ void split_w_detect_kernel(const float* __restrict__ W1,
                                      const float* __restrict__ W2,
                                      const void* __restrict__ nb) {
    if (blockIdx.x == 0 && threadIdx.x == 0) {
        const long long* p = (const long long*)nb;
        int ok64 = 1;
        #pragma unroll
        for (int i = 0; i < 64; i++) {
            long long v = p[i];
            if (v < 0 || v >= (long long)N_NODES) ok64 = 0;
        }
        g_is64 = ok64;
    }
    const int n = D_OUT * KDIM;  // 131072 per matrix
    int i = blockIdx.x * blockDim.x + threadIdx.x;
    if (i < n) {
        split2(W1[i], &g_W1hi[i], &g_W1lo[i]);
        split2(W2[i], &g_W2hi[i], &g_W2lo[i]);
    }
}

// ---------------- launch #2: fp32 -> fp16 feature table ----------------
// fp16 table = 102 MB -> L2-resident during the gather; halves gather bytes.
__global__ void __launch_bounds__(256)
convert_f16_kernel(const float* __restrict__ F) {
    size_t i = (size_t)blockIdx.x * blockDim.x + threadIdx.x;  // float4 index
    const float4* F4 = (const float4*)F;
    float4 v = F4[i];
    __half2 a = __floats2half2_rn(v.x, v.y);
    __half2 b = __floats2half2_rn(v.z, v.w);
    uint2 o;
    o.x = *(uint32_t*)&a;
    o.y = *(uint32_t*)&b;
    ((uint2*)g_F16)[i] = o;
}

// ---------------- launch #3: single-pass gather (fp16 agg, fp32 self) -------
// Warp-per-row: each neighbor row-read = 1 LDG.128/lane (512 B/row fp16).
// Accumulate fp32. Self row read fp32 (exact). Outputs bf16 hi/lo split.
__global__ void __launch_bounds__(256)
gather1_kernel(const float* __restrict__ features,
               const void* __restrict__ nodes_batch,
               const void* __restrict__ neigh2,
               const void* __restrict__ neigh1) {
    const int warp = threadIdx.x >> 5;
    const int lane = threadIdx.x & 31;
    const int m = blockIdx.x * 8 + warp;

    __shared__ int idx[8][K1 + 1];
    if (lane < K1) idx[warp][lane + 1] = get_idx(neigh1, m * K1 + lane);
    if (lane == K1) idx[warp][0] = (m < BATCH) ? get_idx(nodes_batch, m)
                                               : get_idx(neigh2, m - BATCH);
    __syncwarp();

    // agg: fp16 rows, 32 uint4 per row; lane owns halves [lane*8, lane*8+8)
    const uint4* F16 = (const uint4*)g_F16;
    float acc[8];
    #pragma unroll
    for (int j = 0; j < 8; j++) acc[j] = 0.f;
    #pragma unroll 5
    for (int k = 0; k < K1; k++) {
        uint4 v = F16[(size_t)idx[warp][k + 1] * 32 + lane];
        const __half2* h = (const __half2*)&v;
        #pragma unroll
        for (int p = 0; p < 4; p++) {
            float2 f = __half22float2(h[p]);
            acc[2 * p]     += f.x;
            acc[2 * p + 1] += f.y;
        }
    }
    const float s = 1.f / K1;

    // self: fp32 row, lane owns floats [lane*8, lane*8+8)
    const float4* F = (const float4*)features;
    float4 s0 = F[(size_t)idx[warp][0] * 64 + lane * 2];
    float4 s1 = F[(size_t)idx[warp][0] * 64 + lane * 2 + 1];
    float sf[8] = {s0.x, s0.y, s0.z, s0.w, s1.x, s1.y, s1.z, s1.w};

    const size_t base = (size_t)m * KDIM;
    const int c = lane * 8;
    __nv_bfloat16 hi8[8], lo8[8];
    #pragma unroll
    for (int j = 0; j < 8; j++) split2(sf[j], &hi8[j], &lo8[j]);
    *(uint4*)&g_X1hi[base + c] = *(uint4*)hi8;
    *(uint4*)&g_X1lo[base + c] = *(uint4*)lo8;
    #pragma unroll
    for (int j = 0; j < 8; j++) split2(acc[j] * s, &hi8[j], &lo8[j]);
    *(uint4*)&g_X1hi[base + D_IN + c] = *(uint4*)hi8;
    *(uint4*)&g_X1lo[base + D_IN + c] = *(uint4*)lo8;
}

// ---------------- layer-2 concat build -> bf16 split ----------------
__global__ void build_x2_kernel() {
    int b = blockIdx.x;
    int t = threadIdx.x;
    float selfv = g_h1[(size_t)b * D_OUT + t];
    float acc = 0.f;
    #pragma unroll
    for (int j = 0; j < K2; j++)
        acc += g_h1[(size_t)(BATCH + b * K2 + j) * D_OUT + t];
    size_t base = (size_t)b * KDIM;
    split2(selfv,            &g_X2hi[base + t],         &g_X2lo[base + t]);
    split2(acc * (1.f / K2), &g_X2hi[base + D_OUT + t], &g_X2lo[base + D_OUT + t]);
}

// =========================================================================
// mma.sync bf16 GEMM, TERM-FUSED (R12 proven): per K=32 chunk, load
// Ahi/Alo/Whi/Wlo tiles once, accumulate hi*Whi + hi*Wlo + lo*Whi.
// CTA: 128x128, 8 warps 2x4, warp tile 64x32; 2 CTAs/SM; 2-stage ring.
// =========================================================================
#define ASTRIDE   80
#define TILE_B    (128 * ASTRIDE)            // 10240 per tile
#define STAGE     (4 * TILE_B)               // Ahi|Alo|Whi|Wlo = 40960
#define NSTAGE    2
#define GEMM_SMEM (NSTAGE * STAGE)           // 81920
#define NCHUNK    16

__global__ void __launch_bounds__(256, 2)
gemm_bf16x3_kernel(const __nv_bfloat16* __restrict__ Ahi,
                   const __nv_bfloat16* __restrict__ Alo,
                   const __nv_bfloat16* __restrict__ Whi,
                   const __nv_bfloat16* __restrict__ Wlo,
                   float* __restrict__ C) {
    extern __shared__ char smem[];
    const uint32_t smem_b = smem_u32(smem);
    const int tid = threadIdx.x;
    const int l   = tid & 31;
    const int wid = tid >> 5;
    const int wm  = wid >> 2;      // 0..1 (M, 64-row tiles)
    const int wn  = wid & 3;       // 0..3 (N, 32-col tiles)
    const int bm  = (blockIdx.x >> 1) * 128;       // M tile
    const int bn  = (blockIdx.x & 1) * 128;        // N half

    const uint32_t a_l = (uint32_t)((l & 15) * ASTRIDE + (l >> 4) * 16);
    const uint32_t b_l = (uint32_t)((((l >> 4) & 1) * 8 + (l & 7)) * ASTRIDE
                                    + ((l >> 3) & 1) * 16);

    float acc[4][4][4];
    #pragma unroll
    for (int i = 0; i < 4; i++)
        #pragma unroll
        for (int j = 0; j < 4; j++)
            #pragma unroll
            for (int k = 0; k < 4; k++) acc[i][j][k] = 0.f;

    // chunk ck covers K columns [ck*32, ck*32+32) of ALL THREE terms
    auto issue_load = [&](int ck) {
        const int s  = ck & 1;
        const int kb = ck * 32;
        const uint32_t St = smem_b + s * STAGE;
        const int r  = tid >> 1;
        const int c0 = (tid & 1) * 2;
        const size_t arow = (size_t)(bm + r) * KDIM + kb;
        const size_t wrow = (size_t)(bn + r) * KDIM + kb;
        const uint32_t soff = r * ASTRIDE + c0 * 16;
        cp16(St + soff,                   Ahi + arow + c0 * 8);
        cp16(St + soff + 16,              Ahi + arow + c0 * 8 + 8);
        cp16(St + TILE_B + soff,          Alo + arow + c0 * 8);
        cp16(St + TILE_B + soff + 16,     Alo + arow + c0 * 8 + 8);
        cp16(St + 2 * TILE_B + soff,      Whi + wrow + c0 * 8);
        cp16(St + 2 * TILE_B + soff + 16, Whi + wrow + c0 * 8 + 8);
        cp16(St + 3 * TILE_B + soff,      Wlo + wrow + c0 * 8);
        cp16(St + 3 * TILE_B + soff + 16, Wlo + wrow + c0 * 8 + 8);
        cp_commit();
    };

    issue_load(0);

    for (int ck = 0; ck < NCHUNK; ck++) {
        const int s = ck & 1;
        __syncthreads();     // all warps finished computing chunk ck-1 (stage s^1)
        if (ck + 1 < NCHUNK) issue_load(ck + 1);   // writes stage s^1 — safe now
        else                 cp_commit();          // keep group counts consistent
        cp_wait1();          // chunk ck's group complete (only ck+1 pending)
        __syncthreads();     // ck's data visible to all warps

        const uint32_t St = smem_b + s * STAGE;
        #pragma unroll
        for (int ks = 0; ks < 2; ks++) {
            uint32_t af[4][4], bfh[4][2], bfl[4][2];
            const uint32_t ab = St + (uint32_t)(wm * 64 * ASTRIDE + ks * 32) + a_l;
            const uint32_t bb = St + (uint32_t)(2 * TILE_B + wn * 32 * ASTRIDE + ks * 32) + b_l;
            // W fragments: hi and lo tiles
            #pragma unroll
            for (int jp = 0; jp < 2; jp++) {
                uint32_t t4[4];
                ldsm_x4(t4, bb + (uint32_t)(jp * 16 * ASTRIDE));
                bfh[2 * jp][0] = t4[0]; bfh[2 * jp][1] = t4[1];
                bfh[2 * jp + 1][0] = t4[2]; bfh[2 * jp + 1][1] = t4[3];
                ldsm_x4(t4, bb + (uint32_t)(TILE_B + jp * 16 * ASTRIDE));
                bfl[2 * jp][0] = t4[0]; bfl[2 * jp][1] = t4[1];
                bfl[2 * jp + 1][0] = t4[2]; bfl[2 * jp + 1][1] = t4[3];
            }
            // A-hi fragments: used for BOTH Whi and Wlo terms
            #pragma unroll
            for (int mf = 0; mf < 4; mf++)
                ldsm_x4(af[mf], ab + (uint32_t)(mf * 16 * ASTRIDE));
            #pragma unroll
            for (int mf = 0; mf < 4; mf++)
                #pragma unroll
                for (int j = 0; j < 4; j++) {
                    mma16816(acc[mf][j], af[mf], bfh[j]);
                    mma16816(acc[mf][j], af[mf], bfl[j]);
                }
            // A-lo fragments (reuse af registers): term lo*Whi
            #pragma unroll
            for (int mf = 0; mf < 4; mf++)
                ldsm_x4(af[mf], ab + (uint32_t)(TILE_B + mf * 16 * ASTRIDE));
            #pragma unroll
            for (int mf = 0; mf < 4; mf++)
                #pragma unroll
                for (int j = 0; j < 4; j++)
                    mma16816(acc[mf][j], af[mf], bfh[j]);
        }
    }

    // ---- epilogue: fused ReLU, direct f32 stores ----
    const int g  = l >> 2;
    const int t4 = l & 3;
    #pragma unroll
    for (int mf = 0; mf < 4; mf++) {
        const int row0 = bm + wm * 64 + mf * 16 + g;
        #pragma unroll
        for (int j = 0; j < 4; j++) {
            const int col = bn + wn * 32 + j * 8 + t4 * 2;
            float2 v0, v1;
            v0.x = fmaxf(acc[mf][j][0], 0.f);
            v0.y = fmaxf(acc[mf][j][1], 0.f);
            v1.x = fmaxf(acc[mf][j][2], 0.f);
            v1.y = fmaxf(acc[mf][j][3], 0.f);
            *(float2*)&C[(size_t)row0 * D_OUT + col]       = v0;
            *(float2*)&C[(size_t)(row0 + 8) * D_OUT + col] = v1;
        }
    }
}

// ---------------- launch ----------------
extern "C" void kernel_launch(void* const* d_in, const int* in_sizes, int n_in,
                              void* d_out, int out_size) {
    const float* features    = (const float*)d_in[0];
    const float* W1          = (const float*)d_in[1];
    const float* W2          = (const float*)d_in[2];
    const void*  nodes_batch = d_in[3];
    const void*  neigh2      = d_in[4];
    const void*  neigh1      = d_in[5];
    float* out = (float*)d_out;

    __nv_bfloat16 *pX1hi, *pX1lo, *pX2hi, *pX2lo, *pW1hi, *pW1lo, *pW2hi, *pW2lo;
    float* pH1;
    cudaGetSymbolAddress((void**)&pX1hi, g_X1hi);
    cudaGetSymbolAddress((void**)&pX1lo, g_X1lo);
    cudaGetSymbolAddress((void**)&pX2hi, g_X2hi);
    cudaGetSymbolAddress((void**)&pX2lo, g_X2lo);
    cudaGetSymbolAddress((void**)&pW1hi, g_W1hi);
    cudaGetSymbolAddress((void**)&pW1lo, g_W1lo);
    cudaGetSymbolAddress((void**)&pW2hi, g_W2hi);
    cudaGetSymbolAddress((void**)&pW2lo, g_W2lo);
    cudaGetSymbolAddress((void**)&pH1,   g_h1);

    cudaFuncSetAttribute(gemm_bf16x3_kernel,
                         cudaFuncAttributeMaxDynamicSharedMemorySize, GEMM_SMEM);

    // Launch #1: both W splits + dtype probe
    split_w_detect_kernel<<<(D_OUT * KDIM + 255) / 256, 256>>>(W1, W2, nodes_batch);

    // Launch #2: fp32 -> fp16 feature table (102 MB, L2-resident for gather)
    convert_f16_kernel<<<(N_NODES * D_IN / 4 + 255) / 256, 256>>>(features);

    // Launch #3: single-pass gather (fp16 agg + fp32 self)
    gather1_kernel<<<M_L1 / 8, 256>>>(features, nodes_batch, neigh2, neigh1);

    // Launch #4 (ncu-captured slot): h1 = relu(X1 @ W1^T)
    gemm_bf16x3_kernel<<<(M_L1 / 128) * 2, 256, GEMM_SMEM>>>(
        pX1hi, pX1lo, pW1hi, pW1lo, pH1);

    // Launch #5
    build_x2_kernel<<<BATCH, 256>>>();

    // Launch #6: h2 = relu(X2 @ W2^T)
    gemm_bf16x3_kernel<<<(BATCH / 128) * 2, 256, GEMM_SMEM>>>(
        pX2hi, pX2lo, pW2hi, pW2lo, out);
}

// round 14
// speedup vs baseline: 1.0593x; 1.0593x over previous
#include <cuda_runtime.h>
#include <cuda_bf16.h>
#include <cstdint>

#define N_NODES 200000
#define D_IN    256
#define D_OUT   256
#define BATCH   4096
#define K1      25
#define K2      10
#define M_L1    (BATCH * (1 + K2))   // 45056
#define KDIM    512                  // concat(self, agg) width

// ---------------- scratch (no allocations allowed) ----------------
__device__ __align__(16) __nv_bfloat16 g_X1hi[(size_t)M_L1 * KDIM];
__device__ __align__(16) __nv_bfloat16 g_X1lo[(size_t)M_L1 * KDIM];
__device__ __align__(16) float         g_h1[(size_t)M_L1 * D_OUT];
__device__ __align__(16) __nv_bfloat16 g_X2hi[(size_t)BATCH * KDIM];
__device__ __align__(16) __nv_bfloat16 g_X2lo[(size_t)BATCH * KDIM];
__device__ __align__(16) __nv_bfloat16 g_W1hi[(size_t)D_OUT * KDIM];
__device__ __align__(16) __nv_bfloat16 g_W1lo[(size_t)D_OUT * KDIM];
__device__ __align__(16) __nv_bfloat16 g_W2hi[(size_t)D_OUT * KDIM];
__device__ __align__(16) __nv_bfloat16 g_W2lo[(size_t)D_OUT * KDIM];
__device__ int g_is64;

// ================= base-ISA PTX helpers (sm_103 plain, no 'a' features) ======
__device__ __forceinline__ uint32_t smem_u32(const void* p) {
    uint32_t a;
    asm("{ .reg .u64 t; cvta.to.shared.u64 t, %1; cvt.u32.u64 %0, t; }" : "=r"(a) : "l"(p));
    return a;
}
__device__ __forceinline__ void cp16(uint32_t saddr, const void* gaddr) {
    asm volatile("cp.async.cg.shared.global [%0], [%1], 16;" :: "r"(saddr), "l"(gaddr) : "memory");
}
__device__ __forceinline__ void cp_commit() {
    asm volatile("cp.async.commit_group;" ::: "memory");
}
__device__ __forceinline__ void cp_wait1() {
    asm volatile("cp.async.wait_group 1;" ::: "memory");
}
__device__ __forceinline__ void ldsm_x4(uint32_t* r, uint32_t addr) {
    asm volatile("ldmatrix.sync.aligned.m8n8.x4.shared.b16 {%0,%1,%2,%3}, [%4];"
                 : "=r"(r[0]), "=r"(r[1]), "=r"(r[2]), "=r"(r[3]) : "r"(addr));
}
__device__ __forceinline__ void mma16816(float* c, const uint32_t* a, const uint32_t* b) {
    asm volatile("mma.sync.aligned.m16n8k16.row.col.f32.bf16.bf16.f32 "
                 "{%0,%1,%2,%3}, {%4,%5,%6,%7}, {%8,%9}, {%0,%1,%2,%3};"
                 : "+f"(c[0]), "+f"(c[1]), "+f"(c[2]), "+f"(c[3])
                 : "r"(a[0]), "r"(a[1]), "r"(a[2]), "r"(a[3]), "r"(b[0]), "r"(b[1]));
}

__device__ __forceinline__ int get_idx(const void* __restrict__ p, int i) {
    if (g_is64) return (int)((const long long*)p)[i];
    return ((const int*)p)[i];
}

// ---------------- fp32 -> bf16 hi/lo split ----------------
__device__ __forceinline__ void split2(float x, __nv_bfloat16* hi, __nv_bfloat16* lo) {
    __nv_bfloat16 h = __float2bfloat16(x);
    *hi = h;
    *lo = __float2bfloat16(x - __bfloat162float(h));
}

// ---------------- launch #1: split BOTH weight matrices + index-dtype probe --
__global__ void split_w_detect_kernel(const float* __restrict__ W1,
                                      const float* __restrict__ W2,
                                      const void* __restrict__ nb) {
    if (blockIdx.x == 0 && threadIdx.x == 0) {
        const long long* p = (const long long*)nb;
        int ok64 = 1;
        #pragma unroll
        for (int i = 0; i < 64; i++) {
            long long v = p[i];
            if (v < 0 || v >= (long long)N_NODES) ok64 = 0;
        }
        g_is64 = ok64;
    }
    const int n = D_OUT * KDIM;  // 131072 per matrix
    int i = blockIdx.x * blockDim.x + threadIdx.x;
    if (i < n) {
        split2(W1[i], &g_W1hi[i], &g_W1lo[i]);
        split2(W2[i], &g_W2hi[i], &g_W2lo[i]);
    }
}

// ---------------- launches #2,#3: layer-1 gather + mean (column-half) -------
// Warp-per-row, float4 lanes. Column-half passes keep per-pass table
// footprint (102 MB) < L2 (126 MB) -> gather mostly L2-hits.
__global__ void __launch_bounds__(256)
gather1_half_kernel(const float* __restrict__ features,
                    const void* __restrict__ nodes_batch,
                    const void* __restrict__ neigh2,
                    const void* __restrict__ neigh1,
                    int col4_base) {            // 0 or 32 (in float4 units)
    const int warp = threadIdx.x >> 5;
    const int lane = threadIdx.x & 31;
    const int m = blockIdx.x * 8 + warp;

    __shared__ int idx[8][K1 + 1];
    if (lane < K1) idx[warp][lane + 1] = get_idx(neigh1, m * K1 + lane);
    if (lane == K1) idx[warp][0] = (m < BATCH) ? get_idx(nodes_batch, m)
                                               : get_idx(neigh2, m - BATCH);
    __syncwarp();

    const float4* F = (const float4*)features;            // row stride 64
    const int c4 = col4_base + lane;                      // float4 column

    float4 selfv = F[(size_t)idx[warp][0] * 64 + c4];
    float ax = 0.f, ay = 0.f, az = 0.f, aw = 0.f;
    #pragma unroll
    for (int k = 0; k < K1; k++) {
        float4 v = F[(size_t)idx[warp][k + 1] * 64 + c4];
        ax += v.x; ay += v.y; az += v.z; aw += v.w;
    }
    const float s = 1.f / K1;
    float ag[4] = {ax * s, ay * s, az * s, aw * s};
    float sf[4] = {selfv.x, selfv.y, selfv.z, selfv.w};

    const size_t base = (size_t)m * KDIM;
    const int c = c4 * 4;                                 // float column
    __nv_bfloat16 hi4[4], lo4[4];
    #pragma unroll
    for (int j = 0; j < 4; j++) split2(sf[j], &hi4[j], &lo4[j]);
    *(uint2*)&g_X1hi[base + c] = *(uint2*)hi4;
    *(uint2*)&g_X1lo[base + c] = *(uint2*)lo4;
    #pragma unroll
    for (int j = 0; j < 4; j++) split2(ag[j], &hi4[j], &lo4[j]);
    *(uint2*)&g_X1hi[base + D_IN + c] = *(uint2*)hi4;
    *(uint2*)&g_X1lo[base + D_IN + c] = *(uint2*)lo4;
}

// ---------------- layer-2 concat build -> bf16 split (warp-per-row float4) --
__global__ void __launch_bounds__(256)
build_x2_kernel() {
    const int warp = threadIdx.x >> 5;
    const int lane = threadIdx.x & 31;
    const int b = blockIdx.x * 8 + warp;

    const float4* H = (const float4*)g_h1;                // row stride 64
    const size_t base = (size_t)b * KDIM;
    #pragma unroll
    for (int seg = 0; seg < 2; seg++) {
        const int c4 = lane + seg * 32;
        float4 sv = H[(size_t)b * 64 + c4];
        float ax = 0.f, ay = 0.f, az = 0.f, aw = 0.f;
        #pragma unroll
        for (int j = 0; j < K2; j++) {
            float4 v = H[(size_t)(BATCH + b * K2 + j) * 64 + c4];
            ax += v.x; ay += v.y; az += v.z; aw += v.w;
        }
        const float s = 1.f / K2;
        float sf[4] = {sv.x, sv.y, sv.z, sv.w};
        float ag[4] = {ax * s, ay * s, az * s, aw * s};
        const int c = c4 * 4;
        __nv_bfloat16 hi4[4], lo4[4];
        #pragma unroll
        for (int j = 0; j < 4; j++) split2(sf[j], &hi4[j], &lo4[j]);
        *(uint2*)&g_X2hi[base + c] = *(uint2*)hi4;
        *(uint2*)&g_X2lo[base + c] = *(uint2*)lo4;
        #pragma unroll
        for (int j = 0; j < 4; j++) split2(ag[j], &hi4[j], &lo4[j]);
        *(uint2*)&g_X2hi[base + D_OUT + c] = *(uint2*)hi4;
        *(uint2*)&g_X2lo[base + D_OUT + c] = *(uint2*)lo4;
    }
}

// =========================================================================
// mma.sync bf16 GEMM, TERM-FUSED (R12) + warp-parity ks stagger: odd warps
// process ks=1 first, desynchronizing the post-barrier ldsm bursts so half
// the warps feed MMAs while the other half read smem.
// CTA: 128x128, 8 warps 2x4, warp tile 64x32; 2 CTAs/SM; 2-stage ring.
// =========================================================================
#define ASTRIDE   80
#define TILE_B    (128 * ASTRIDE)            // 10240 per tile
#define STAGE     (4 * TILE_B)               // Ahi|Alo|Whi|Wlo = 40960
#define NSTAGE    2
#define GEMM_SMEM (NSTAGE * STAGE)           // 81920
#define NCHUNK    16

__global__ void __launch_bounds__(256, 2)
gemm_bf16x3_kernel(const __nv_bfloat16* __restrict__ Ahi,
                   const __nv_bfloat16* __restrict__ Alo,
                   const __nv_bfloat16* __restrict__ Whi,
                   const __nv_bfloat16* __restrict__ Wlo,
                   float* __restrict__ C) {
    extern __shared__ char smem[];
    const uint32_t smem_b = smem_u32(smem);
    const int tid = threadIdx.x;
    const int l   = tid & 31;
    const int wid = tid >> 5;
    const int wm  = wid >> 2;      // 0..1 (M, 64-row tiles)
    const int wn  = wid & 3;       // 0..3 (N, 32-col tiles)
    const int bm  = (blockIdx.x >> 1) * 128;       // M tile
    const int bn  = (blockIdx.x & 1) * 128;        // N half
    const int ksx = wid & 1;       // ks visit order stagger

    const uint32_t a_l = (uint32_t)((l & 15) * ASTRIDE + (l >> 4) * 16);
    const uint32_t b_l = (uint32_t)((((l >> 4) & 1) * 8 + (l & 7)) * ASTRIDE
                                    + ((l >> 3) & 1) * 16);

    float acc[4][4][4];
    #pragma unroll
    for (int i = 0; i < 4; i++)
        #pragma unroll
        for (int j = 0; j < 4; j++)
            #pragma unroll
            for (int k = 0; k < 4; k++) acc[i][j][k] = 0.f;

    // chunk ck covers K columns [ck*32, ck*32+32) of ALL THREE terms
    auto issue_load = [&](int ck) {
        const int s  = ck & 1;
        const int kb = ck * 32;
        const uint32_t St = smem_b + s * STAGE;
        const int r  = tid >> 1;
        const int c0 = (tid & 1) * 2;
        const size_t arow = (size_t)(bm + r) * KDIM + kb;
        const size_t wrow = (size_t)(bn + r) * KDIM + kb;
        const uint32_t soff = r * ASTRIDE + c0 * 16;
        cp16(St + soff,                   Ahi + arow + c0 * 8);
        cp16(St + soff + 16,              Ahi + arow + c0 * 8 + 8);
        cp16(St + TILE_B + soff,          Alo + arow + c0 * 8);
        cp16(St + TILE_B + soff + 16,     Alo + arow + c0 * 8 + 8);
        cp16(St + 2 * TILE_B + soff,      Whi + wrow + c0 * 8);
        cp16(St + 2 * TILE_B + soff + 16, Whi + wrow + c0 * 8 + 8);
        cp16(St + 3 * TILE_B + soff,      Wlo + wrow + c0 * 8);
        cp16(St + 3 * TILE_B + soff + 16, Wlo + wrow + c0 * 8 + 8);
        cp_commit();
    };

    issue_load(0);

    for (int ck = 0; ck < NCHUNK; ck++) {
        const int s = ck & 1;
        __syncthreads();     // all warps finished computing chunk ck-1 (stage s^1)
        if (ck + 1 < NCHUNK) issue_load(ck + 1);   // writes stage s^1 — safe now
        else                 cp_commit();          // keep group counts consistent
        cp_wait1();          // chunk ck's group complete (only ck+1 pending)
        __syncthreads();     // ck's data visible to all warps

        const uint32_t St = smem_b + s * STAGE;
        #pragma unroll
        for (int kk = 0; kk < 2; kk++) {
            const int ks = kk ^ ksx;   // warp-parity stagger
            uint32_t af[4][4], bfh[4][2], bfl[4][2];
            const uint32_t ab = St + (uint32_t)(wm * 64 * ASTRIDE + ks * 32) + a_l;
            const uint32_t bb = St + (uint32_t)(2 * TILE_B + wn * 32 * ASTRIDE + ks * 32) + b_l;
            // W fragments: hi and lo tiles
            #pragma unroll
            for (int jp = 0; jp < 2; jp++) {
                uint32_t t4[4];
                ldsm_x4(t4, bb + (uint32_t)(jp * 16 * ASTRIDE));
                bfh[2 * jp][0] = t4[0]; bfh[2 * jp][1] = t4[1];
                bfh[2 * jp + 1][0] = t4[2]; bfh[2 * jp + 1][1] = t4[3];
                ldsm_x4(t4, bb + (uint32_t)(TILE_B + jp * 16 * ASTRIDE));
                bfl[2 * jp][0] = t4[0]; bfl[2 * jp][1] = t4[1];
                bfl[2 * jp + 1][0] = t4[2]; bfl[2 * jp + 1][1] = t4[3];
            }
            // A-hi fragments: used for BOTH Whi and Wlo terms
            #pragma unroll
            for (int mf = 0; mf < 4; mf++)
                ldsm_x4(af[mf], ab + (uint32_t)(mf * 16 * ASTRIDE));
            #pragma unroll
            for (int mf = 0; mf < 4; mf++)
                #pragma unroll
                for (int j = 0; j < 4; j++) {
                    mma16816(acc[mf][j], af[mf], bfh[j]);
                    mma16816(acc[mf][j], af[mf], bfl[j]);
                }
            // A-lo fragments (reuse af registers): term lo*Whi
            #pragma unroll
            for (int mf = 0; mf < 4; mf++)
                ldsm_x4(af[mf], ab + (uint32_t)(TILE_B + mf * 16 * ASTRIDE));
            #pragma unroll
            for (int mf = 0; mf < 4; mf++)
                #pragma unroll
                for (int j = 0; j < 4; j++)
                    mma16816(acc[mf][j], af[mf], bfh[j]);
        }
    }

    // ---- epilogue: fused ReLU, direct f32 stores ----
    const int g  = l >> 2;
    const int t4 = l & 3;
    #pragma unroll
    for (int mf = 0; mf < 4; mf++) {
        const int row0 = bm + wm * 64 + mf * 16 + g;
        #pragma unroll
        for (int j = 0; j < 4; j++) {
            const int col = bn + wn * 32 + j * 8 + t4 * 2;
            float2 v0, v1;
            v0.x = fmaxf(acc[mf][j][0], 0.f);
            v0.y = fmaxf(acc[mf][j][1], 0.f);
            v1.x = fmaxf(acc[mf][j][2], 0.f);
            v1.y = fmaxf(acc[mf][j][3], 0.f);
            *(float2*)&C[(size_t)row0 * D_OUT + col]       = v0;
            *(float2*)&C[(size_t)(row0 + 8) * D_OUT + col] = v1;
        }
    }
}

// ---------------- launch ----------------
extern "C" void kernel_launch(void* const* d_in, const int* in_sizes, int n_in,
                              void* d_out, int out_size) {
    const float* features    = (const float*)d_in[0];
    const float* W1          = (const float*)d_in[1];
    const float* W2          = (const float*)d_in[2];
    const void*  nodes_batch = d_in[3];
    const void*  neigh2      = d_in[4];
    const void*  neigh1      = d_in[5];
    float* out = (float*)d_out;

    __nv_bfloat16 *pX1hi, *pX1lo, *pX2hi, *pX2lo, *pW1hi, *pW1lo, *pW2hi, *pW2lo;
    float* pH1;
    cudaGetSymbolAddress((void**)&pX1hi, g_X1hi);
    cudaGetSymbolAddress((void**)&pX1lo, g_X1lo);
    cudaGetSymbolAddress((void**)&pX2hi, g_X2hi);
    cudaGetSymbolAddress((void**)&pX2lo, g_X2lo);
    cudaGetSymbolAddress((void**)&pW1hi, g_W1hi);
    cudaGetSymbolAddress((void**)&pW1lo, g_W1lo);
    cudaGetSymbolAddress((void**)&pW2hi, g_W2hi);
    cudaGetSymbolAddress((void**)&pW2lo, g_W2lo);
    cudaGetSymbolAddress((void**)&pH1,   g_h1);

    cudaFuncSetAttribute(gemm_bf16x3_kernel,
                         cudaFuncAttributeMaxDynamicSharedMemorySize, GEMM_SMEM);

    // Launch #1: both W splits + dtype probe
    split_w_detect_kernel<<<(D_OUT * KDIM + 255) / 256, 256>>>(W1, W2, nodes_batch);

    // Launches #2,#3: gather (two column-half passes; warp-per-row float4)
    gather1_half_kernel<<<M_L1 / 8, 256>>>(features, nodes_batch, neigh2, neigh1, 0);
    gather1_half_kernel<<<M_L1 / 8, 256>>>(features, nodes_batch, neigh2, neigh1, 32);

    // Launch #4 (ncu-captured slot): h1 = relu(X1 @ W1^T)
    gemm_bf16x3_kernel<<<(M_L1 / 128) * 2, 256, GEMM_SMEM>>>(
        pX1hi, pX1lo, pW1hi, pW1lo, pH1);

    // Launch #5
    build_x2_kernel<<<BATCH / 8, 256>>>();

    // Launch #6: h2 = relu(X2 @ W2^T)
    gemm_bf16x3_kernel<<<(BATCH / 128) * 2, 256, GEMM_SMEM>>>(
        pX2hi, pX2lo, pW2hi, pW2lo, out);
}

// round 15
// speedup vs baseline: 1.2350x; 1.1658x over previous
#include <cuda_runtime.h>
#include <cuda_fp16.h>
#include <cstdint>

#define N_NODES 200000
#define D_IN    256
#define D_OUT   256
#define BATCH   4096
#define K1      25
#define K2      10
#define M_L1    (BATCH * (1 + K2))   // 45056
#define KDIM    512                  // concat(self, agg) width

// ---------------- scratch (no allocations allowed) ----------------
__device__ __align__(16) __half g_X1hi[(size_t)M_L1 * KDIM];
__device__ __align__(16) __half g_X1lo[(size_t)M_L1 * KDIM];
__device__ __align__(16) float  g_h1[(size_t)M_L1 * D_OUT];
__device__ __align__(16) __half g_X2hi[(size_t)BATCH * KDIM];
__device__ __align__(16) __half g_X2lo[(size_t)BATCH * KDIM];
__device__ __align__(16) __half g_W1h[(size_t)D_OUT * KDIM];
__device__ __align__(16) __half g_W2h[(size_t)D_OUT * KDIM];
__device__ int g_is64;

// ================= base-ISA PTX helpers (sm_103 plain, no 'a' features) ======
__device__ __forceinline__ uint32_t smem_u32(const void* p) {
    uint32_t a;
    asm("{ .reg .u64 t; cvta.to.shared.u64 t, %1; cvt.u32.u64 %0, t; }" : "=r"(a) : "l"(p));
    return a;
}
__device__ __forceinline__ void cp16(uint32_t saddr, const void* gaddr) {
    asm volatile("cp.async.cg.shared.global [%0], [%1], 16;" :: "r"(saddr), "l"(gaddr) : "memory");
}
__device__ __forceinline__ void cp_commit() {
    asm volatile("cp.async.commit_group;" ::: "memory");
}
__device__ __forceinline__ void cp_wait1() {
    asm volatile("cp.async.wait_group 1;" ::: "memory");
}
__device__ __forceinline__ void ldsm_x4(uint32_t* r, uint32_t addr) {
    asm volatile("ldmatrix.sync.aligned.m8n8.x4.shared.b16 {%0,%1,%2,%3}, [%4];"
                 : "=r"(r[0]), "=r"(r[1]), "=r"(r[2]), "=r"(r[3]) : "r"(addr));
}
// fp16 x fp16 -> fp32 MMA (exact products, f32 accumulate)
__device__ __forceinline__ void mma16816(float* c, const uint32_t* a, const uint32_t* b) {
    asm volatile("mma.sync.aligned.m16n8k16.row.col.f32.f16.f16.f32 "
                 "{%0,%1,%2,%3}, {%4,%5,%6,%7}, {%8,%9}, {%0,%1,%2,%3};"
                 : "+f"(c[0]), "+f"(c[1]), "+f"(c[2]), "+f"(c[3])
                 : "r"(a[0]), "r"(a[1]), "r"(a[2]), "r"(a[3]), "r"(b[0]), "r"(b[1]));
}

__device__ __forceinline__ int get_idx(const void* __restrict__ p, int i) {
    if (g_is64) return (int)((const long long*)p)[i];
    return ((const int*)p)[i];
}

// ---------------- fp32 -> fp16 hi/lo split (A operand, ~22-bit exact) -------
__device__ __forceinline__ void split2h(float x, __half* hi, __half* lo) {
    __half h = __float2half_rn(x);
    *hi = h;
    *lo = __float2half_rn(x - __half2float(h));
}

// ---------------- launch #1: round W to fp16 + index-dtype probe ------------
__global__ void split_w_detect_kernel(const float* __restrict__ W1,
                                      const float* __restrict__ W2,
                                      const void* __restrict__ nb) {
    if (blockIdx.x == 0 && threadIdx.x == 0) {
        const long long* p = (const long long*)nb;
        int ok64 = 1;
        #pragma unroll
        for (int i = 0; i < 64; i++) {
            long long v = p[i];
            if (v < 0 || v >= (long long)N_NODES) ok64 = 0;
        }
        g_is64 = ok64;
    }
    const int n = D_OUT * KDIM;  // 131072 per matrix
    int i = blockIdx.x * blockDim.x + threadIdx.x;
    if (i < n) {
        g_W1h[i] = __float2half_rn(W1[i]);
        g_W2h[i] = __float2half_rn(W2[i]);
    }
}

// ---------------- launches #2,#3: layer-1 gather + mean (column-half) -------
// Warp-per-row, float4 lanes. Column-half passes keep per-pass table
// footprint (102 MB) < L2 (126 MB) -> gather mostly L2-hits.
__global__ void __launch_bounds__(256)
gather1_half_kernel(const float* __restrict__ features,
                    const void* __restrict__ nodes_batch,
                    const void* __restrict__ neigh2,
                    const void* __restrict__ neigh1,
                    int col4_base) {            // 0 or 32 (in float4 units)
    const int warp = threadIdx.x >> 5;
    const int lane = threadIdx.x & 31;
    const int m = blockIdx.x * 8 + warp;

    __shared__ int idx[8][K1 + 1];
    if (lane < K1) idx[warp][lane + 1] = get_idx(neigh1, m * K1 + lane);
    if (lane == K1) idx[warp][0] = (m < BATCH) ? get_idx(nodes_batch, m)
                                               : get_idx(neigh2, m - BATCH);
    __syncwarp();

    const float4* F = (const float4*)features;            // row stride 64
    const int c4 = col4_base + lane;                      // float4 column

    float4 selfv = F[(size_t)idx[warp][0] * 64 + c4];
    float ax = 0.f, ay = 0.f, az = 0.f, aw = 0.f;
    #pragma unroll
    for (int k = 0; k < K1; k++) {
        float4 v = F[(size_t)idx[warp][k + 1] * 64 + c4];
        ax += v.x; ay += v.y; az += v.z; aw += v.w;
    }
    const float s = 1.f / K1;
    float ag[4] = {ax * s, ay * s, az * s, aw * s};
    float sf[4] = {selfv.x, selfv.y, selfv.z, selfv.w};

    const size_t base = (size_t)m * KDIM;
    const int c = c4 * 4;                                 // float column
    __half hi4[4], lo4[4];
    #pragma unroll
    for (int j = 0; j < 4; j++) split2h(sf[j], &hi4[j], &lo4[j]);
    *(uint2*)&g_X1hi[base + c] = *(uint2*)hi4;
    *(uint2*)&g_X1lo[base + c] = *(uint2*)lo4;
    #pragma unroll
    for (int j = 0; j < 4; j++) split2h(ag[j], &hi4[j], &lo4[j]);
    *(uint2*)&g_X1hi[base + D_IN + c] = *(uint2*)hi4;
    *(uint2*)&g_X1lo[base + D_IN + c] = *(uint2*)lo4;
}

// ---------------- layer-2 concat build -> fp16 split (warp-per-row float4) --
__global__ void __launch_bounds__(256)
build_x2_kernel() {
    const int warp = threadIdx.x >> 5;
    const int lane = threadIdx.x & 31;
    const int b = blockIdx.x * 8 + warp;

    const float4* H = (const float4*)g_h1;                // row stride 64
    const size_t base = (size_t)b * KDIM;
    #pragma unroll
    for (int seg = 0; seg < 2; seg++) {
        const int c4 = lane + seg * 32;
        float4 sv = H[(size_t)b * 64 + c4];
        float ax = 0.f, ay = 0.f, az = 0.f, aw = 0.f;
        #pragma unroll
        for (int j = 0; j < K2; j++) {
            float4 v = H[(size_t)(BATCH + b * K2 + j) * 64 + c4];
            ax += v.x; ay += v.y; az += v.z; aw += v.w;
        }
        const float s = 1.f / K2;
        float sf[4] = {sv.x, sv.y, sv.z, sv.w};
        float ag[4] = {ax * s, ay * s, az * s, aw * s};
        const int c = c4 * 4;
        __half hi4[4], lo4[4];
        #pragma unroll
        for (int j = 0; j < 4; j++) split2h(sf[j], &hi4[j], &lo4[j]);
        *(uint2*)&g_X2hi[base + c] = *(uint2*)hi4;
        *(uint2*)&g_X2lo[base + c] = *(uint2*)lo4;
        #pragma unroll
        for (int j = 0; j < 4; j++) split2h(ag[j], &hi4[j], &lo4[j]);
        *(uint2*)&g_X2hi[base + D_OUT + c] = *(uint2*)hi4;
        *(uint2*)&g_X2lo[base + D_OUT + c] = *(uint2*)lo4;
    }
}

// =========================================================================
// mma.sync fp16 GEMM, 2-TERM: C = relu( (Ahi + Alo) @ Wh^T ).
// A split hi/lo fp16 (~22-bit exact); W rounded to fp16 (err ~2^-12).
// CTA: 128x128, 8 warps 2x4, warp tile 64x32; 2 CTAs/SM.
// 3 smem tiles/stage (Ahi|Alo|Wh), 3-stage ring, prefetch 2,
// one __syncthreads per chunk, warp-parity ks stagger.
// =========================================================================
#define ASTRIDE   80
#define TILE_B    (128 * ASTRIDE)            // 10240 per tile
#define STAGE     (3 * TILE_B)               // Ahi|Alo|Wh = 30720
#define NSTAGE    3
#define GEMM_SMEM (NSTAGE * STAGE)           // 92160
#define NCHUNK    16

__global__ void __launch_bounds__(256, 2)
gemm_f16x2_kernel(const __half* __restrict__ Ahi,
                  const __half* __restrict__ Alo,
                  const __half* __restrict__ Wh,
                  float* __restrict__ C) {
    extern __shared__ char smem[];
    const uint32_t smem_b = smem_u32(smem);
    const int tid = threadIdx.x;
    const int l   = tid & 31;
    const int wid = tid >> 5;
    const int wm  = wid >> 2;      // 0..1 (M, 64-row tiles)
    const int wn  = wid & 3;       // 0..3 (N, 32-col tiles)
    const int bm  = (blockIdx.x >> 1) * 128;       // M tile
    const int bn  = (blockIdx.x & 1) * 128;        // N half
    const int ksx = wid & 1;       // ks visit order stagger

    const uint32_t a_l = (uint32_t)((l & 15) * ASTRIDE + (l >> 4) * 16);
    const uint32_t b_l = (uint32_t)((((l >> 4) & 1) * 8 + (l & 7)) * ASTRIDE
                                    + ((l >> 3) & 1) * 16);

    float acc[4][4][4];
    #pragma unroll
    for (int i = 0; i < 4; i++)
        #pragma unroll
        for (int j = 0; j < 4; j++)
            #pragma unroll
            for (int k = 0; k < 4; k++) acc[i][j][k] = 0.f;

    // chunk ck covers K columns [ck*32, ck*32+32) of both terms
    auto issue_load = [&](int ck) {
        const int s  = ck % NSTAGE;
        const int kb = ck * 32;
        const uint32_t St = smem_b + s * STAGE;
        const int r  = tid >> 1;
        const int c0 = (tid & 1) * 2;
        const size_t arow = (size_t)(bm + r) * KDIM + kb;
        const size_t wrow = (size_t)(bn + r) * KDIM + kb;
        const uint32_t soff = r * ASTRIDE + c0 * 16;
        cp16(St + soff,                   Ahi + arow + c0 * 8);
        cp16(St + soff + 16,              Ahi + arow + c0 * 8 + 8);
        cp16(St + TILE_B + soff,          Alo + arow + c0 * 8);
        cp16(St + TILE_B + soff + 16,     Alo + arow + c0 * 8 + 8);
        cp16(St + 2 * TILE_B + soff,      Wh + wrow + c0 * 8);
        cp16(St + 2 * TILE_B + soff + 16, Wh + wrow + c0 * 8 + 8);
        cp_commit();
    };

    issue_load(0);
    issue_load(1);

    for (int ck = 0; ck < NCHUNK; ck++) {
        const int s = ck % NSTAGE;
        cp_wait1();          // chunk ck landed (<=1 group pending)
        __syncthreads();     // all warps done with chunk ck-1's stage

        const int nk = ck + 2;
        if (nk < NCHUNK) issue_load(nk);   // writes stage (ck-1)%3 — fenced above
        else             cp_commit();      // keep group counts consistent

        const uint32_t St = smem_b + s * STAGE;
        #pragma unroll
        for (int kk = 0; kk < 2; kk++) {
            const int ks = kk ^ ksx;   // warp-parity stagger
            uint32_t af[4][4], bfh[4][2];
            const uint32_t ab = St + (uint32_t)(wm * 64 * ASTRIDE + ks * 32) + a_l;
            const uint32_t bb = St + (uint32_t)(2 * TILE_B + wn * 32 * ASTRIDE + ks * 32) + b_l;
            // W fragments (hi only)
            #pragma unroll
            for (int jp = 0; jp < 2; jp++) {
                uint32_t t4[4];
                ldsm_x4(t4, bb + (uint32_t)(jp * 16 * ASTRIDE));
                bfh[2 * jp][0] = t4[0]; bfh[2 * jp][1] = t4[1];
                bfh[2 * jp + 1][0] = t4[2]; bfh[2 * jp + 1][1] = t4[3];
            }
            // A-hi fragments
            #pragma unroll
            for (int mf = 0; mf < 4; mf++)
                ldsm_x4(af[mf], ab + (uint32_t)(mf * 16 * ASTRIDE));
            #pragma unroll
            for (int mf = 0; mf < 4; mf++)
                #pragma unroll
                for (int j = 0; j < 4; j++)
                    mma16816(acc[mf][j], af[mf], bfh[j]);
            // A-lo fragments (reuse af registers)
            #pragma unroll
            for (int mf = 0; mf < 4; mf++)
                ldsm_x4(af[mf], ab + (uint32_t)(TILE_B + mf * 16 * ASTRIDE));
            #pragma unroll
            for (int mf = 0; mf < 4; mf++)
                #pragma unroll
                for (int j = 0; j < 4; j++)
                    mma16816(acc[mf][j], af[mf], bfh[j]);
        }
    }

    // ---- epilogue: fused ReLU, direct f32 stores ----
    const int g  = l >> 2;
    const int t4 = l & 3;
    #pragma unroll
    for (int mf = 0; mf < 4; mf++) {
        const int row0 = bm + wm * 64 + mf * 16 + g;
        #pragma unroll
        for (int j = 0; j < 4; j++) {
            const int col = bn + wn * 32 + j * 8 + t4 * 2;
            float2 v0, v1;
            v0.x = fmaxf(acc[mf][j][0], 0.f);
            v0.y = fmaxf(acc[mf][j][1], 0.f);
            v1.x = fmaxf(acc[mf][j][2], 0.f);
            v1.y = fmaxf(acc[mf][j][3], 0.f);
            *(float2*)&C[(size_t)row0 * D_OUT + col]       = v0;
            *(float2*)&C[(size_t)(row0 + 8) * D_OUT + col] = v1;
        }
    }
}

// ---------------- launch ----------------
extern "C" void kernel_launch(void* const* d_in, const int* in_sizes, int n_in,
                              void* d_out, int out_size) {
    const float* features    = (const float*)d_in[0];
    const float* W1          = (const float*)d_in[1];
    const float* W2          = (const float*)d_in[2];
    const void*  nodes_batch = d_in[3];
    const void*  neigh2      = d_in[4];
    const void*  neigh1      = d_in[5];
    float* out = (float*)d_out;

    __half *pX1hi, *pX1lo, *pX2hi, *pX2lo, *pW1h, *pW2h;
    float* pH1;
    cudaGetSymbolAddress((void**)&pX1hi, g_X1hi);
    cudaGetSymbolAddress((void**)&pX1lo, g_X1lo);
    cudaGetSymbolAddress((void**)&pX2hi, g_X2hi);
    cudaGetSymbolAddress((void**)&pX2lo, g_X2lo);
    cudaGetSymbolAddress((void**)&pW1h,  g_W1h);
    cudaGetSymbolAddress((void**)&pW2h,  g_W2h);
    cudaGetSymbolAddress((void**)&pH1,   g_h1);

    cudaFuncSetAttribute(gemm_f16x2_kernel,
                         cudaFuncAttributeMaxDynamicSharedMemorySize, GEMM_SMEM);

    // Launch #1: W -> fp16 + dtype probe
    split_w_detect_kernel<<<(D_OUT * KDIM + 255) / 256, 256>>>(W1, W2, nodes_batch);

    // Launches #2,#3: gather (two column-half passes; warp-per-row float4)
    gather1_half_kernel<<<M_L1 / 8, 256>>>(features, nodes_batch, neigh2, neigh1, 0);
    gather1_half_kernel<<<M_L1 / 8, 256>>>(features, nodes_batch, neigh2, neigh1, 32);

    // Launch #4 (ncu-captured slot): h1 = relu(X1 @ W1^T)
    gemm_f16x2_kernel<<<(M_L1 / 128) * 2, 256, GEMM_SMEM>>>(
        pX1hi, pX1lo, pW1h, pH1);

    // Launch #5
    build_x2_kernel<<<BATCH / 8, 256>>>();

    // Launch #6: h2 = relu(X2 @ W2^T)
    gemm_f16x2_kernel<<<(BATCH / 128) * 2, 256, GEMM_SMEM>>>(
        pX2hi, pX2lo, pW2h, out);
}

// round 16
// speedup vs baseline: 1.2390x; 1.0032x over previous
#include <cuda_runtime.h>
#include <cuda_fp16.h>
#include <cstdint>

#define N_NODES 200000
#define D_IN    256
#define D_OUT   256
#define BATCH   4096
#define K1      25
#define K2      10
#define M_L1    (BATCH * (1 + K2))   // 45056
#define KDIM    512                  // concat(self, agg) width

// ---------------- scratch (no allocations allowed) ----------------
__device__ __align__(16) __half g_X1hi[(size_t)M_L1 * KDIM];
__device__ __align__(16) __half g_X1lo[(size_t)M_L1 * KDIM];
__device__ __align__(16) float  g_h1[(size_t)M_L1 * D_OUT];
__device__ __align__(16) __half g_X2hi[(size_t)BATCH * KDIM];
__device__ __align__(16) __half g_X2lo[(size_t)BATCH * KDIM];
__device__ __align__(16) __half g_W1h[(size_t)D_OUT * KDIM];
__device__ __align__(16) __half g_W2h[(size_t)D_OUT * KDIM];
__device__ int g_is64;

// ================= base-ISA PTX helpers (sm_103 plain, no 'a' features) ======
__device__ __forceinline__ uint32_t smem_u32(const void* p) {
    uint32_t a;
    asm("{ .reg .u64 t; cvta.to.shared.u64 t, %1; cvt.u32.u64 %0, t; }" : "=r"(a) : "l"(p));
    return a;
}
__device__ __forceinline__ void cp16(uint32_t saddr, const void* gaddr) {
    asm volatile("cp.async.cg.shared.global [%0], [%1], 16;" :: "r"(saddr), "l"(gaddr) : "memory");
}
__device__ __forceinline__ void cp_commit() {
    asm volatile("cp.async.commit_group;" ::: "memory");
}
__device__ __forceinline__ void cp_wait1() {
    asm volatile("cp.async.wait_group 1;" ::: "memory");
}
__device__ __forceinline__ void ldsm_x4(uint32_t* r, uint32_t addr) {
    asm volatile("ldmatrix.sync.aligned.m8n8.x4.shared.b16 {%0,%1,%2,%3}, [%4];"
                 : "=r"(r[0]), "=r"(r[1]), "=r"(r[2]), "=r"(r[3]) : "r"(addr));
}
// fp16 x fp16 -> fp32 MMA (exact products, f32 accumulate)
__device__ __forceinline__ void mma16816(float* c, const uint32_t* a, const uint32_t* b) {
    asm volatile("mma.sync.aligned.m16n8k16.row.col.f32.f16.f16.f32 "
                 "{%0,%1,%2,%3}, {%4,%5,%6,%7}, {%8,%9}, {%0,%1,%2,%3};"
                 : "+f"(c[0]), "+f"(c[1]), "+f"(c[2]), "+f"(c[3])
                 : "r"(a[0]), "r"(a[1]), "r"(a[2]), "r"(a[3]), "r"(b[0]), "r"(b[1]));
}

__device__ __forceinline__ int get_idx(const void* __restrict__ p, int i) {
    if (g_is64) return (int)((const long long*)p)[i];
    return ((const int*)p)[i];
}

// ---------------- fp32 -> fp16 hi/lo split (A operand, ~22-bit exact) -------
__device__ __forceinline__ void split2h(float x, __half* hi, __half* lo) {
    __half h = __float2half_rn(x);
    *hi = h;
    *lo = __float2half_rn(x - __half2float(h));
}

// ---------------- launch #1: round W to fp16 + index-dtype probe ------------
__global__ void split_w_detect_kernel(const float* __restrict__ W1,
                                      const float* __restrict__ W2,
                                      const void* __restrict__ nb) {
    if (blockIdx.x == 0 && threadIdx.x == 0) {
        const long long* p = (const long long*)nb;
        int ok64 = 1;
        #pragma unroll
        for (int i = 0; i < 64; i++) {
            long long v = p[i];
            if (v < 0 || v >= (long long)N_NODES) ok64 = 0;
        }
        g_is64 = ok64;
    }
    const int n = D_OUT * KDIM;  // 131072 per matrix
    int i = blockIdx.x * blockDim.x + threadIdx.x;
    if (i < n) {
        g_W1h[i] = __float2half_rn(W1[i]);
        g_W2h[i] = __float2half_rn(W2[i]);
    }
}

// ---------------- launches #2,#3: layer-1 gather + mean (column-half) -------
// Warp-per-row, float4 lanes. Column-half passes keep per-pass table
// footprint (102 MB) < L2 (126 MB) -> gather mostly L2-hits (at roofline).
__global__ void __launch_bounds__(256)
gather1_half_kernel(const float* __restrict__ features,
                    const void* __restrict__ nodes_batch,
                    const void* __restrict__ neigh2,
                    const void* __restrict__ neigh1,
                    int col4_base) {            // 0 or 32 (in float4 units)
    const int warp = threadIdx.x >> 5;
    const int lane = threadIdx.x & 31;
    const int m = blockIdx.x * 8 + warp;

    __shared__ int idx[8][K1 + 1];
    if (lane < K1) idx[warp][lane + 1] = get_idx(neigh1, m * K1 + lane);
    if (lane == K1) idx[warp][0] = (m < BATCH) ? get_idx(nodes_batch, m)
                                               : get_idx(neigh2, m - BATCH);
    __syncwarp();

    const float4* F = (const float4*)features;            // row stride 64
    const int c4 = col4_base + lane;                      // float4 column

    float4 selfv = F[(size_t)idx[warp][0] * 64 + c4];
    float ax = 0.f, ay = 0.f, az = 0.f, aw = 0.f;
    #pragma unroll
    for (int k = 0; k < K1; k++) {
        float4 v = F[(size_t)idx[warp][k + 1] * 64 + c4];
        ax += v.x; ay += v.y; az += v.z; aw += v.w;
    }
    const float s = 1.f / K1;
    float ag[4] = {ax * s, ay * s, az * s, aw * s};
    float sf[4] = {selfv.x, selfv.y, selfv.z, selfv.w};

    const size_t base = (size_t)m * KDIM;
    const int c = c4 * 4;                                 // float column
    __half hi4[4], lo4[4];
    #pragma unroll
    for (int j = 0; j < 4; j++) split2h(sf[j], &hi4[j], &lo4[j]);
    *(uint2*)&g_X1hi[base + c] = *(uint2*)hi4;
    *(uint2*)&g_X1lo[base + c] = *(uint2*)lo4;
    #pragma unroll
    for (int j = 0; j < 4; j++) split2h(ag[j], &hi4[j], &lo4[j]);
    *(uint2*)&g_X1hi[base + D_IN + c] = *(uint2*)hi4;
    *(uint2*)&g_X1lo[base + D_IN + c] = *(uint2*)lo4;
}

// ---------------- layer-2 concat build -> fp16 split (warp-per-row float4) --
__global__ void __launch_bounds__(256)
build_x2_kernel() {
    const int warp = threadIdx.x >> 5;
    const int lane = threadIdx.x & 31;
    const int b = blockIdx.x * 8 + warp;

    const float4* H = (const float4*)g_h1;                // row stride 64
    const size_t base = (size_t)b * KDIM;
    #pragma unroll
    for (int seg = 0; seg < 2; seg++) {
        const int c4 = lane + seg * 32;
        float4 sv = H[(size_t)b * 64 + c4];
        float ax = 0.f, ay = 0.f, az = 0.f, aw = 0.f;
        #pragma unroll
        for (int j = 0; j < K2; j++) {
            float4 v = H[(size_t)(BATCH + b * K2 + j) * 64 + c4];
            ax += v.x; ay += v.y; az += v.z; aw += v.w;
        }
        const float s = 1.f / K2;
        float sf[4] = {sv.x, sv.y, sv.z, sv.w};
        float ag[4] = {ax * s, ay * s, az * s, aw * s};
        const int c = c4 * 4;
        __half hi4[4], lo4[4];
        #pragma unroll
        for (int j = 0; j < 4; j++) split2h(sf[j], &hi4[j], &lo4[j]);
        *(uint2*)&g_X2hi[base + c] = *(uint2*)hi4;
        *(uint2*)&g_X2lo[base + c] = *(uint2*)lo4;
        #pragma unroll
        for (int j = 0; j < 4; j++) split2h(ag[j], &hi4[j], &lo4[j]);
        *(uint2*)&g_X2hi[base + D_OUT + c] = *(uint2*)hi4;
        *(uint2*)&g_X2lo[base + D_OUT + c] = *(uint2*)lo4;
    }
}

// =========================================================================
// mma.sync fp16 GEMM, 2-TERM: C = relu( (Ahi + Alo) @ Wh^T ).
// CTA: 128x128, 8 warps in 4x2 grid, warp tile 32x64 — A smem redundancy
// x2 (vs x4 in 2x4), total crossbar reads 64KB/chunk (-20%).
// 3 smem tiles/stage (Ahi|Alo|Wh), 3-stage ring, prefetch 2,
// one __syncthreads per chunk, warp-parity ks stagger. 2 CTAs/SM.
// =========================================================================
#define ASTRIDE   80
#define TILE_B    (128 * ASTRIDE)            // 10240 per tile
#define STAGE     (3 * TILE_B)               // Ahi|Alo|Wh = 30720
#define NSTAGE    3
#define GEMM_SMEM (NSTAGE * STAGE)           // 92160
#define NCHUNK    16

__global__ void __launch_bounds__(256, 2)
gemm_f16x2_kernel(const __half* __restrict__ Ahi,
                  const __half* __restrict__ Alo,
                  const __half* __restrict__ Wh,
                  float* __restrict__ C) {
    extern __shared__ char smem[];
    const uint32_t smem_b = smem_u32(smem);
    const int tid = threadIdx.x;
    const int l   = tid & 31;
    const int wid = tid >> 5;
    const int wm  = wid >> 1;      // 0..3 (M, 32-row tiles)
    const int wn  = wid & 1;       // 0..1 (N, 64-col tiles)
    const int bm  = (blockIdx.x >> 1) * 128;       // M tile
    const int bn  = (blockIdx.x & 1) * 128;        // N half
    const int ksx = wid & 1;       // ks visit order stagger

    const uint32_t a_l = (uint32_t)((l & 15) * ASTRIDE + (l >> 4) * 16);
    const uint32_t b_l = (uint32_t)((((l >> 4) & 1) * 8 + (l & 7)) * ASTRIDE
                                    + ((l >> 3) & 1) * 16);

    float acc[2][8][4];
    #pragma unroll
    for (int i = 0; i < 2; i++)
        #pragma unroll
        for (int j = 0; j < 8; j++)
            #pragma unroll
            for (int k = 0; k < 4; k++) acc[i][j][k] = 0.f;

    // chunk ck covers K columns [ck*32, ck*32+32) of both terms
    auto issue_load = [&](int ck) {
        const int s  = ck % NSTAGE;
        const int kb = ck * 32;
        const uint32_t St = smem_b + s * STAGE;
        const int r  = tid >> 1;
        const int c0 = (tid & 1) * 2;
        const size_t arow = (size_t)(bm + r) * KDIM + kb;
        const size_t wrow = (size_t)(bn + r) * KDIM + kb;
        const uint32_t soff = r * ASTRIDE + c0 * 16;
        cp16(St + soff,                   Ahi + arow + c0 * 8);
        cp16(St + soff + 16,              Ahi + arow + c0 * 8 + 8);
        cp16(St + TILE_B + soff,          Alo + arow + c0 * 8);
        cp16(St + TILE_B + soff + 16,     Alo + arow + c0 * 8 + 8);
        cp16(St + 2 * TILE_B + soff,      Wh + wrow + c0 * 8);
        cp16(St + 2 * TILE_B + soff + 16, Wh + wrow + c0 * 8 + 8);
        cp_commit();
    };

    issue_load(0);
    issue_load(1);

    for (int ck = 0; ck < NCHUNK; ck++) {
        const int s = ck % NSTAGE;
        cp_wait1();          // chunk ck landed (<=1 group pending)
        __syncthreads();     // all warps done with chunk ck-1's stage

        const int nk = ck + 2;
        if (nk < NCHUNK) issue_load(nk);   // writes stage (ck-1)%3 — fenced above
        else             cp_commit();      // keep group counts consistent

        const uint32_t St = smem_b + s * STAGE;
        #pragma unroll
        for (int kk = 0; kk < 2; kk++) {
            const int ks = kk ^ ksx;   // warp-parity stagger
            uint32_t af[2][4], bfh[8][2];
            const uint32_t ab = St + (uint32_t)(wm * 32 * ASTRIDE + ks * 32) + a_l;
            const uint32_t bb = St + (uint32_t)(2 * TILE_B + wn * 64 * ASTRIDE + ks * 32) + b_l;
            // W fragments: 64 cols -> 4 ldsm_x4, reused by both A terms
            #pragma unroll
            for (int jp = 0; jp < 4; jp++) {
                uint32_t t4[4];
                ldsm_x4(t4, bb + (uint32_t)(jp * 16 * ASTRIDE));
                bfh[2 * jp][0] = t4[0]; bfh[2 * jp][1] = t4[1];
                bfh[2 * jp + 1][0] = t4[2]; bfh[2 * jp + 1][1] = t4[3];
            }
            // A-hi fragments (32 rows -> 2 ldsm_x4)
            #pragma unroll
            for (int mf = 0; mf < 2; mf++)
                ldsm_x4(af[mf], ab + (uint32_t)(mf * 16 * ASTRIDE));
            #pragma unroll
            for (int mf = 0; mf < 2; mf++)
                #pragma unroll
                for (int j = 0; j < 8; j++)
                    mma16816(acc[mf][j], af[mf], bfh[j]);
            // A-lo fragments (reuse af registers)
            #pragma unroll
            for (int mf = 0; mf < 2; mf++)
                ldsm_x4(af[mf], ab + (uint32_t)(TILE_B + mf * 16 * ASTRIDE));
            #pragma unroll
            for (int mf = 0; mf < 2; mf++)
                #pragma unroll
                for (int j = 0; j < 8; j++)
                    mma16816(acc[mf][j], af[mf], bfh[j]);
        }
    }

    // ---- epilogue: fused ReLU, direct f32 stores ----
    const int g  = l >> 2;
    const int t4 = l & 3;
    #pragma unroll
    for (int mf = 0; mf < 2; mf++) {
        const int row0 = bm + wm * 32 + mf * 16 + g;
        #pragma unroll
        for (int j = 0; j < 8; j++) {
            const int col = bn + wn * 64 + j * 8 + t4 * 2;
            float2 v0, v1;
            v0.x = fmaxf(acc[mf][j][0], 0.f);
            v0.y = fmaxf(acc[mf][j][1], 0.f);
            v1.x = fmaxf(acc[mf][j][2], 0.f);
            v1.y = fmaxf(acc[mf][j][3], 0.f);
            *(float2*)&C[(size_t)row0 * D_OUT + col]       = v0;
            *(float2*)&C[(size_t)(row0 + 8) * D_OUT + col] = v1;
        }
    }
}

// ---------------- launch ----------------
extern "C" void kernel_launch(void* const* d_in, const int* in_sizes, int n_in,
                              void* d_out, int out_size) {
    const float* features    = (const float*)d_in[0];
    const float* W1          = (const float*)d_in[1];
    const float* W2          = (const float*)d_in[2];
    const void*  nodes_batch = d_in[3];
    const void*  neigh2      = d_in[4];
    const void*  neigh1      = d_in[5];
    float* out = (float*)d_out;

    __half *pX1hi, *pX1lo, *pX2hi, *pX2lo, *pW1h, *pW2h;
    float* pH1;
    cudaGetSymbolAddress((void**)&pX1hi, g_X1hi);
    cudaGetSymbolAddress((void**)&pX1lo, g_X1lo);
    cudaGetSymbolAddress((void**)&pX2hi, g_X2hi);
    cudaGetSymbolAddress((void**)&pX2lo, g_X2lo);
    cudaGetSymbolAddress((void**)&pW1h,  g_W1h);
    cudaGetSymbolAddress((void**)&pW2h,  g_W2h);
    cudaGetSymbolAddress((void**)&pH1,   g_h1);

    cudaFuncSetAttribute(gemm_f16x2_kernel,
                         cudaFuncAttributeMaxDynamicSharedMemorySize, GEMM_SMEM);

    // Launch #1: W -> fp16 + dtype probe
    split_w_detect_kernel<<<(D_OUT * KDIM + 255) / 256, 256>>>(W1, W2, nodes_batch);

    // Launches #2,#3: gather (two column-half passes; warp-per-row float4)
    gather1_half_kernel<<<M_L1 / 8, 256>>>(features, nodes_batch, neigh2, neigh1, 0);
    gather1_half_kernel<<<M_L1 / 8, 256>>>(features, nodes_batch, neigh2, neigh1, 32);

    // Launch #4 (ncu-captured slot): h1 = relu(X1 @ W1^T)
    gemm_f16x2_kernel<<<(M_L1 / 128) * 2, 256, GEMM_SMEM>>>(
        pX1hi, pX1lo, pW1h, pH1);

    // Launch #5
    build_x2_kernel<<<BATCH / 8, 256>>>();

    // Launch #6: h2 = relu(X2 @ W2^T)
    gemm_f16x2_kernel<<<(BATCH / 128) * 2, 256, GEMM_SMEM>>>(
        pX2hi, pX2lo, pW2h, out);
}

// round 17
// speedup vs baseline: 1.2431x; 1.0033x over previous
#include <cuda_runtime.h>
#include <cuda_fp16.h>
#include <cstdint>

#define N_NODES 200000
#define D_IN    256
#define D_OUT   256
#define BATCH   4096
#define K1      25
#define K2      10
#define M_L1    (BATCH * (1 + K2))   // 45056
#define KDIM    512                  // concat(self, agg) width

// ---------------- scratch (no allocations allowed) ----------------
__device__ __align__(16) __half g_X1hi[(size_t)M_L1 * KDIM];
__device__ __align__(16) __half g_X1lo[(size_t)M_L1 * KDIM];
__device__ __align__(16) float  g_h1[(size_t)M_L1 * D_OUT];
__device__ __align__(16) __half g_X2hi[(size_t)BATCH * KDIM];
__device__ __align__(16) __half g_X2lo[(size_t)BATCH * KDIM];
__device__ __align__(16) __half g_W1h[(size_t)D_OUT * KDIM];
__device__ __align__(16) __half g_W2h[(size_t)D_OUT * KDIM];
__device__ int g_is64;

// ================= base-ISA PTX helpers (sm_103 plain, no 'a' features) ======
__device__ __forceinline__ uint32_t smem_u32(const void* p) {
    uint32_t a;
    asm("{ .reg .u64 t; cvta.to.shared.u64 t, %1; cvt.u32.u64 %0, t; }" : "=r"(a) : "l"(p));
    return a;
}
__device__ __forceinline__ void cp16(uint32_t saddr, const void* gaddr) {
    asm volatile("cp.async.cg.shared.global [%0], [%1], 16;" :: "r"(saddr), "l"(gaddr) : "memory");
}
__device__ __forceinline__ void cp_commit() {
    asm volatile("cp.async.commit_group;" ::: "memory");
}
__device__ __forceinline__ void cp_wait1() {
    asm volatile("cp.async.wait_group 1;" ::: "memory");
}
__device__ __forceinline__ void ldsm_x4(uint32_t* r, uint32_t addr) {
    asm volatile("ldmatrix.sync.aligned.m8n8.x4.shared.b16 {%0,%1,%2,%3}, [%4];"
                 : "=r"(r[0]), "=r"(r[1]), "=r"(r[2]), "=r"(r[3]) : "r"(addr));
}
// fp16 x fp16 -> fp32 MMA (exact products, f32 accumulate)
__device__ __forceinline__ void mma16816(float* c, const uint32_t* a, const uint32_t* b) {
    asm volatile("mma.sync.aligned.m16n8k16.row.col.f32.f16.f16.f32 "
                 "{%0,%1,%2,%3}, {%4,%5,%6,%7}, {%8,%9}, {%0,%1,%2,%3};"
                 : "+f"(c[0]), "+f"(c[1]), "+f"(c[2]), "+f"(c[3])
                 : "r"(a[0]), "r"(a[1]), "r"(a[2]), "r"(a[3]), "r"(b[0]), "r"(b[1]));
}
// streaming (evict-first) stores: keep the L2-resident feature table warm
__device__ __forceinline__ void stcs_u2(void* p, uint2 v) {
    asm volatile("st.global.cs.v2.u32 [%0], {%1,%2};" :: "l"(p), "r"(v.x), "r"(v.y) : "memory");
}
__device__ __forceinline__ void stcs_u4(void* p, uint4 v) {
    asm volatile("st.global.cs.v4.u32 [%0], {%1,%2,%3,%4};"
                 :: "l"(p), "r"(v.x), "r"(v.y), "r"(v.z), "r"(v.w) : "memory");
}
__device__ __forceinline__ void stcs_f2(void* p, float2 v) {
    asm volatile("st.global.cs.v2.f32 [%0], {%1,%2};" :: "l"(p), "f"(v.x), "f"(v.y) : "memory");
}

__device__ __forceinline__ int get_idx(const void* __restrict__ p, int i) {
    if (g_is64) return (int)((const long long*)p)[i];
    return ((const int*)p)[i];
}

// ---------------- fp32 -> fp16 hi/lo split (A operand, ~22-bit exact) -------
__device__ __forceinline__ void split2h(float x, __half* hi, __half* lo) {
    __half h = __float2half_rn(x);
    *hi = h;
    *lo = __float2half_rn(x - __half2float(h));
}

// ---------------- launch #1: round W to fp16 + index-dtype probe ------------
__global__ void split_w_detect_kernel(const float* __restrict__ W1,
                                      const float* __restrict__ W2,
                                      const void* __restrict__ nb) {
    if (blockIdx.x == 0 && threadIdx.x == 0) {
        const long long* p = (const long long*)nb;
        int ok64 = 1;
        #pragma unroll
        for (int i = 0; i < 64; i++) {
            long long v = p[i];
            if (v < 0 || v >= (long long)N_NODES) ok64 = 0;
        }
        g_is64 = ok64;
    }
    const int n = D_OUT * KDIM;  // 131072 per matrix
    int i = blockIdx.x * blockDim.x + threadIdx.x;
    if (i < n) {
        g_W1h[i] = __float2half_rn(W1[i]);
        g_W2h[i] = __float2half_rn(W2[i]);
    }
}

// ---------------- launches #2,#3: layer-1 gather + mean (column-half) -------
// Warp-per-row, float4 lanes. Column-half passes keep per-pass table
// footprint (102 MB) < L2 (126 MB). X1 outputs stored with .cs so the
// streaming writes don't evict the feature table from L2.
__global__ void __launch_bounds__(256)
gather1_half_kernel(const float* __restrict__ features,
                    const void* __restrict__ nodes_batch,
                    const void* __restrict__ neigh2,
                    const void* __restrict__ neigh1,
                    int col4_base) {            // 0 or 32 (in float4 units)
    const int warp = threadIdx.x >> 5;
    const int lane = threadIdx.x & 31;
    const int m = blockIdx.x * 8 + warp;

    __shared__ int idx[8][K1 + 1];
    if (lane < K1) idx[warp][lane + 1] = get_idx(neigh1, m * K1 + lane);
    if (lane == K1) idx[warp][0] = (m < BATCH) ? get_idx(nodes_batch, m)
                                               : get_idx(neigh2, m - BATCH);
    __syncwarp();

    const float4* F = (const float4*)features;            // row stride 64
    const int c4 = col4_base + lane;                      // float4 column

    float4 selfv = F[(size_t)idx[warp][0] * 64 + c4];
    float ax = 0.f, ay = 0.f, az = 0.f, aw = 0.f;
    #pragma unroll
    for (int k = 0; k < K1; k++) {
        float4 v = F[(size_t)idx[warp][k + 1] * 64 + c4];
        ax += v.x; ay += v.y; az += v.z; aw += v.w;
    }
    const float s = 1.f / K1;
    float ag[4] = {ax * s, ay * s, az * s, aw * s};
    float sf[4] = {selfv.x, selfv.y, selfv.z, selfv.w};

    const size_t base = (size_t)m * KDIM;
    const int c = c4 * 4;                                 // float column
    __half hi4[4], lo4[4];
    #pragma unroll
    for (int j = 0; j < 4; j++) split2h(sf[j], &hi4[j], &lo4[j]);
    stcs_u2(&g_X1hi[base + c], *(uint2*)hi4);
    stcs_u2(&g_X1lo[base + c], *(uint2*)lo4);
    #pragma unroll
    for (int j = 0; j < 4; j++) split2h(ag[j], &hi4[j], &lo4[j]);
    stcs_u2(&g_X1hi[base + D_IN + c], *(uint2*)hi4);
    stcs_u2(&g_X1lo[base + D_IN + c], *(uint2*)lo4);
}

// ---------------- layer-2 concat build -> fp16 split (warp-per-row float4) --
__global__ void __launch_bounds__(256)
build_x2_kernel() {
    const int warp = threadIdx.x >> 5;
    const int lane = threadIdx.x & 31;
    const int b = blockIdx.x * 8 + warp;

    const float4* H = (const float4*)g_h1;                // row stride 64
    const size_t base = (size_t)b * KDIM;
    #pragma unroll
    for (int seg = 0; seg < 2; seg++) {
        const int c4 = lane + seg * 32;
        float4 sv = H[(size_t)b * 64 + c4];
        float ax = 0.f, ay = 0.f, az = 0.f, aw = 0.f;
        #pragma unroll
        for (int j = 0; j < K2; j++) {
            float4 v = H[(size_t)(BATCH + b * K2 + j) * 64 + c4];
            ax += v.x; ay += v.y; az += v.z; aw += v.w;
        }
        const float s = 1.f / K2;
        float sf[4] = {sv.x, sv.y, sv.z, sv.w};
        float ag[4] = {ax * s, ay * s, az * s, aw * s};
        const int c = c4 * 4;
        __half hi4[4], lo4[4];
        #pragma unroll
        for (int j = 0; j < 4; j++) split2h(sf[j], &hi4[j], &lo4[j]);
        stcs_u2(&g_X2hi[base + c], *(uint2*)hi4);
        stcs_u2(&g_X2lo[base + c], *(uint2*)lo4);
        #pragma unroll
        for (int j = 0; j < 4; j++) split2h(ag[j], &hi4[j], &lo4[j]);
        stcs_u2(&g_X2hi[base + D_OUT + c], *(uint2*)hi4);
        stcs_u2(&g_X2lo[base + D_OUT + c], *(uint2*)lo4);
    }
}

// =========================================================================
// mma.sync fp16 GEMM, 2-TERM (R15/R16 proven): C = relu( (Ahi+Alo) @ Wh^T ).
// CTA: 128x128, 8 warps 4x2, warp tile 32x64; 2 CTAs/SM.
// 3 smem tiles/stage, 3-stage ring, prefetch 2, 1 barrier/chunk, ks stagger.
// Epilogue stores with .cs (h1/out are streaming, read-once).
// =========================================================================
#define ASTRIDE   80
#define TILE_B    (128 * ASTRIDE)            // 10240 per tile
#define STAGE     (3 * TILE_B)               // Ahi|Alo|Wh = 30720
#define NSTAGE    3
#define GEMM_SMEM (NSTAGE * STAGE)           // 92160
#define NCHUNK    16

__global__ void __launch_bounds__(256, 2)
gemm_f16x2_kernel(const __half* __restrict__ Ahi,
                  const __half* __restrict__ Alo,
                  const __half* __restrict__ Wh,
                  float* __restrict__ C) {
    extern __shared__ char smem[];
    const uint32_t smem_b = smem_u32(smem);
    const int tid = threadIdx.x;
    const int l   = tid & 31;
    const int wid = tid >> 5;
    const int wm  = wid >> 1;      // 0..3 (M, 32-row tiles)
    const int wn  = wid & 1;       // 0..1 (N, 64-col tiles)
    const int bm  = (blockIdx.x >> 1) * 128;       // M tile
    const int bn  = (blockIdx.x & 1) * 128;        // N half
    const int ksx = wid & 1;       // ks visit order stagger

    const uint32_t a_l = (uint32_t)((l & 15) * ASTRIDE + (l >> 4) * 16);
    const uint32_t b_l = (uint32_t)((((l >> 4) & 1) * 8 + (l & 7)) * ASTRIDE
                                    + ((l >> 3) & 1) * 16);

    float acc[2][8][4];
    #pragma unroll
    for (int i = 0; i < 2; i++)
        #pragma unroll
        for (int j = 0; j < 8; j++)
            #pragma unroll
            for (int k = 0; k < 4; k++) acc[i][j][k] = 0.f;

    // chunk ck covers K columns [ck*32, ck*32+32) of both terms
    auto issue_load = [&](int ck) {
        const int s  = ck % NSTAGE;
        const int kb = ck * 32;
        const uint32_t St = smem_b + s * STAGE;
        const int r  = tid >> 1;
        const int c0 = (tid & 1) * 2;
        const size_t arow = (size_t)(bm + r) * KDIM + kb;
        const size_t wrow = (size_t)(bn + r) * KDIM + kb;
        const uint32_t soff = r * ASTRIDE + c0 * 16;
        cp16(St + soff,                   Ahi + arow + c0 * 8);
        cp16(St + soff + 16,              Ahi + arow + c0 * 8 + 8);
        cp16(St + TILE_B + soff,          Alo + arow + c0 * 8);
        cp16(St + TILE_B + soff + 16,     Alo + arow + c0 * 8 + 8);
        cp16(St + 2 * TILE_B + soff,      Wh + wrow + c0 * 8);
        cp16(St + 2 * TILE_B + soff + 16, Wh + wrow + c0 * 8 + 8);
        cp_commit();
    };

    issue_load(0);
    issue_load(1);

    for (int ck = 0; ck < NCHUNK; ck++) {
        const int s = ck % NSTAGE;
        cp_wait1();          // chunk ck landed (<=1 group pending)
        __syncthreads();     // all warps done with chunk ck-1's stage

        const int nk = ck + 2;
        if (nk < NCHUNK) issue_load(nk);   // writes stage (ck-1)%3 — fenced above
        else             cp_commit();      // keep group counts consistent

        const uint32_t St = smem_b + s * STAGE;
        #pragma unroll
        for (int kk = 0; kk < 2; kk++) {
            const int ks = kk ^ ksx;   // warp-parity stagger
            uint32_t af[2][4], bfh[8][2];
            const uint32_t ab = St + (uint32_t)(wm * 32 * ASTRIDE + ks * 32) + a_l;
            const uint32_t bb = St + (uint32_t)(2 * TILE_B + wn * 64 * ASTRIDE + ks * 32) + b_l;
            // W fragments: 64 cols -> 4 ldsm_x4, reused by both A terms
            #pragma unroll
            for (int jp = 0; jp < 4; jp++) {
                uint32_t t4[4];
                ldsm_x4(t4, bb + (uint32_t)(jp * 16 * ASTRIDE));
                bfh[2 * jp][0] = t4[0]; bfh[2 * jp][1] = t4[1];
                bfh[2 * jp + 1][0] = t4[2]; bfh[2 * jp + 1][1] = t4[3];
            }
            // A-hi fragments (32 rows -> 2 ldsm_x4)
            #pragma unroll
            for (int mf = 0; mf < 2; mf++)
                ldsm_x4(af[mf], ab + (uint32_t)(mf * 16 * ASTRIDE));
            #pragma unroll
            for (int mf = 0; mf < 2; mf++)
                #pragma unroll
                for (int j = 0; j < 8; j++)
                    mma16816(acc[mf][j], af[mf], bfh[j]);
            // A-lo fragments (reuse af registers)
            #pragma unroll
            for (int mf = 0; mf < 2; mf++)
                ldsm_x4(af[mf], ab + (uint32_t)(TILE_B + mf * 16 * ASTRIDE));
            #pragma unroll
            for (int mf = 0; mf < 2; mf++)
                #pragma unroll
                for (int j = 0; j < 8; j++)
                    mma16816(acc[mf][j], af[mf], bfh[j]);
        }
    }

    // ---- epilogue: fused ReLU, streaming f32 stores ----
    const int g  = l >> 2;
    const int t4 = l & 3;
    #pragma unroll
    for (int mf = 0; mf < 2; mf++) {
        const int row0 = bm + wm * 32 + mf * 16 + g;
        #pragma unroll
        for (int j = 0; j < 8; j++) {
            const int col = bn + wn * 64 + j * 8 + t4 * 2;
            float2 v0, v1;
            v0.x = fmaxf(acc[mf][j][0], 0.f);
            v0.y = fmaxf(acc[mf][j][1], 0.f);
            v1.x = fmaxf(acc[mf][j][2], 0.f);
            v1.y = fmaxf(acc[mf][j][3], 0.f);
            stcs_f2(&C[(size_t)row0 * D_OUT + col],       v0);
            stcs_f2(&C[(size_t)(row0 + 8) * D_OUT + col], v1);
        }
    }
}

// ---------------- launch ----------------
extern "C" void kernel_launch(void* const* d_in, const int* in_sizes, int n_in,
                              void* d_out, int out_size) {
    const float* features    = (const float*)d_in[0];
    const float* W1          = (const float*)d_in[1];
    const float* W2          = (const float*)d_in[2];
    const void*  nodes_batch = d_in[3];
    const void*  neigh2      = d_in[4];
    const void*  neigh1      = d_in[5];
    float* out = (float*)d_out;

    __half *pX1hi, *pX1lo, *pX2hi, *pX2lo, *pW1h, *pW2h;
    float* pH1;
    cudaGetSymbolAddress((void**)&pX1hi, g_X1hi);
    cudaGetSymbolAddress((void**)&pX1lo, g_X1lo);
    cudaGetSymbolAddress((void**)&pX2hi, g_X2hi);
    cudaGetSymbolAddress((void**)&pX2lo, g_X2lo);
    cudaGetSymbolAddress((void**)&pW1h,  g_W1h);
    cudaGetSymbolAddress((void**)&pW2h,  g_W2h);
    cudaGetSymbolAddress((void**)&pH1,   g_h1);

    cudaFuncSetAttribute(gemm_f16x2_kernel,
                         cudaFuncAttributeMaxDynamicSharedMemorySize, GEMM_SMEM);

    // Launch #1: W -> fp16 + dtype probe
    split_w_detect_kernel<<<(D_OUT * KDIM + 255) / 256, 256>>>(W1, W2, nodes_batch);

    // Launches #2,#3: gather (two column-half passes; warp-per-row float4)
    gather1_half_kernel<<<M_L1 / 8, 256>>>(features, nodes_batch, neigh2, neigh1, 0);
    gather1_half_kernel<<<M_L1 / 8, 256>>>(features, nodes_batch, neigh2, neigh1, 32);

    // Launch #4 (ncu-captured slot): h1 = relu(X1 @ W1^T)
    gemm_f16x2_kernel<<<(M_L1 / 128) * 2, 256, GEMM_SMEM>>>(
        pX1hi, pX1lo, pW1h, pH1);

    // Launch #5
    build_x2_kernel<<<BATCH / 8, 256>>>();

    // Launch #6: h2 = relu(X2 @ W2^T)
    gemm_f16x2_kernel<<<(BATCH / 128) * 2, 256, GEMM_SMEM>>>(
        pX2hi, pX2lo, pW2h, out);
}